// round 6
// baseline (speedup 1.0000x reference)
#include <cuda_runtime.h>
#include <cuda_fp16.h>
#include <cstddef>
#include <cstdint>

#define BB   256
#define PP   256
#define ENCD 256
#define DECD 512
#define EE   256
#define VV   5000
#define TT   96
#define GG   2048
#define VPAD 5120
#define NB   148          // persistent grid size (<= SM count on B300/GB300)
#define SMEMSZ 65536

// ---------------- device scratch ----------------
__device__ __half g_att1[(size_t)BB * PP * DECD];
__device__ __half g_encb[(size_t)BB * PP * ENCD];
__device__ float  g_embW[(size_t)VV * GG];
__device__ __half g_emb16[(size_t)VV * EE];
__device__ __half g_hall[(size_t)BB * TT * DECD];   // t-major: [(t*BB+b)*DECD+d]
__device__ __half g_xh[BB * (ENCD + DECD)];         // [xg | h], ld=768
__device__ float  g_h[BB * DECD];
__device__ float  g_c[2 * BB * DECD];
__device__ float  g_ag[BB * 768];
__device__ float  g_gates[BB * GG];
__device__ __half g_mean16[BB * ENCD];
__device__ float  g_bag[768];
__device__ __half g_wag[512 * 768];
__device__ __half g_wg[768 * GG];
__device__ __half g_wtop[256 * GG];
__device__ __half g_wfc[512 * VPAD];
__device__ __half g_wenc[256 * 512];
__device__ __half g_wih0[256 * 512];
__device__ __half g_wic0[256 * 512];

// grid barrier state (count self-resets; gen is monotonic across launches/replays)
__device__ unsigned g_bar_count;
__device__ unsigned g_bar_gen;

__device__ __forceinline__ float sigmoidf(float x) { return 1.f / (1.f + expf(-x)); }

// ================= PTX helpers =================
__device__ __forceinline__ uint32_t smem_u32(const void* p) {
    return (uint32_t)__cvta_generic_to_shared(p);
}
__device__ __forceinline__ void cp16(void* dst, const void* src) {
    asm volatile("cp.async.cg.shared.global [%0], [%1], 16;"
                 :: "r"(smem_u32(dst)), "l"(src));
}
__device__ __forceinline__ void cp_commit() { asm volatile("cp.async.commit_group;"); }
template<int N>
__device__ __forceinline__ void cp_wait() { asm volatile("cp.async.wait_group %0;" :: "n"(N)); }

__device__ __forceinline__ void ldm_x4(uint32_t* r, uint32_t addr) {
    asm volatile("ldmatrix.sync.aligned.m8n8.x4.shared.b16 {%0,%1,%2,%3}, [%4];"
                 : "=r"(r[0]), "=r"(r[1]), "=r"(r[2]), "=r"(r[3]) : "r"(addr));
}
__device__ __forceinline__ void ldm_x4_t(uint32_t* r, uint32_t addr) {
    asm volatile("ldmatrix.sync.aligned.m8n8.x4.trans.shared.b16 {%0,%1,%2,%3}, [%4];"
                 : "=r"(r[0]), "=r"(r[1]), "=r"(r[2]), "=r"(r[3]) : "r"(addr));
}
__device__ __forceinline__ void mma16816(float* c, const uint32_t* a, const uint32_t* b) {
    asm volatile("mma.sync.aligned.m16n8k16.row.col.f32.f16.f16.f32 "
                 "{%0,%1,%2,%3},{%4,%5,%6,%7},{%8,%9},{%0,%1,%2,%3};"
                 : "+f"(c[0]), "+f"(c[1]), "+f"(c[2]), "+f"(c[3])
                 : "r"(a[0]), "r"(a[1]), "r"(a[2]), "r"(a[3]), "r"(b[0]), "r"(b[1]));
}

// software grid barrier (all NB blocks resident)
__device__ __forceinline__ void gbar() {
    __threadfence();
    __syncthreads();
    if (threadIdx.x == 0) {
        unsigned my = *((volatile unsigned*)&g_bar_gen);
        unsigned a = atomicAdd(&g_bar_count, 1u);
        if (a == NB - 1) {
            g_bar_count = 0;
            __threadfence();
            atomicAdd(&g_bar_gen, 1u);
        } else {
            while (*((volatile unsigned*)&g_bar_gen) == my) { __nanosleep(64); }
        }
    }
    __syncthreads();
}

// ================= in-kernel pipelined TC tile =================
// Computes a BMx128 tile (BM = 32*MF) of A[m0.., lda] @ W[.., n0.., ldw], K multiple of 64.
template<int MF>
__device__ __forceinline__ void tile_compute(
    __half* smbuf, const __half* __restrict__ A, int lda,
    const __half* __restrict__ W, int ldw,
    int m0, int n0, int K, float acc[MF][4][4])
{
    constexpr int BM = MF * 32;
    constexpr int ASTG = BM * 64;
    __half* As = smbuf;
    __half* Bs = smbuf + 2 * ASTG;
    const int tid = threadIdx.x;
    const int warp = tid >> 5, lane = tid & 31;
    const int wm = (warp & 1) * (BM / 2);
    const int wn = (warp >> 1) * 32;

#pragma unroll
    for (int i = 0; i < MF; i++)
#pragma unroll
        for (int j = 0; j < 4; j++)
#pragma unroll
            for (int k = 0; k < 4; k++) acc[i][j][k] = 0.f;

    const int nk = K >> 6;

#define MLOAD_A(stage, kc)                                                      \
    {                                                                           \
        _Pragma("unroll")                                                       \
        for (int i = 0; i < MF; i++) {                                          \
            int idx = tid + i * 256;                                            \
            int r = idx >> 3, c = idx & 7;                                      \
            cp16(As + (stage) * ASTG + r * 64 + (((c ^ r) & 7) << 3),           \
                 A + (size_t)(m0 + r) * lda + (kc) + c * 8);                    \
        }                                                                       \
    }
#define MLOAD_B(stage, kc)                                                      \
    {                                                                           \
        _Pragma("unroll")                                                       \
        for (int i = 0; i < 4; i++) {                                           \
            int idx = tid + i * 256;                                            \
            int r = idx >> 4, c = idx & 15;                                     \
            int sw = (c & 8) | ((c ^ r) & 7);                                   \
            cp16(Bs + (stage) * 8192 + r * 128 + (sw << 3),                     \
                 W + (size_t)((kc) + r) * ldw + n0 + c * 8);                    \
        }                                                                       \
    }

    MLOAD_A(0, 0); MLOAD_B(0, 0); cp_commit();

    for (int k = 0; k < nk; k++) {
        int cur = k & 1;
        if (k + 1 < nk) {
            MLOAD_A(cur ^ 1, (k + 1) * 64);
            MLOAD_B(cur ^ 1, (k + 1) * 64);
            cp_commit();
            cp_wait<1>();
        } else {
            cp_wait<0>();
        }
        __syncthreads();
        const __half* Ab = As + cur * ASTG;
        const __half* Bb = Bs + cur * 8192;
#pragma unroll
        for (int ks = 0; ks < 4; ks++) {
            uint32_t a[MF][4], b[2][4];
#pragma unroll
            for (int mi = 0; mi < MF; mi++) {
                int m = wm + mi * 16 + (lane & 15);
                int kch = ks * 2 + (lane >> 4);
                ldm_x4(a[mi], smem_u32(Ab + m * 64 + (((kch ^ m) & 7) << 3)));
            }
#pragma unroll
            for (int ni = 0; ni < 2; ni++) {
                int kk = ks * 16 + (lane & 15);
                int nch = (wn >> 3) + ni * 2 + (lane >> 4);
                int sw = (nch & 8) | ((nch ^ kk) & 7);
                ldm_x4_t(b[ni], smem_u32(Bb + kk * 128 + (sw << 3)));
            }
#pragma unroll
            for (int mi = 0; mi < MF; mi++)
#pragma unroll
                for (int ni = 0; ni < 4; ni++)
                    mma16816(acc[mi][ni], a[mi], &b[ni >> 1][(ni & 1) * 2]);
        }
        __syncthreads();
    }
#undef MLOAD_A
#undef MLOAD_B
}

// ================= attention unit (one batch element) =================
__device__ __forceinline__ void attention_unit(
    int b, int t, const float* __restrict__ wfull,
    const int* __restrict__ lens, float* __restrict__ alphas_out, float* smf)
{
    float* att2s = smf;          // 512
    float* wf    = smf + 512;    // 512
    float* es    = smf + 1024;   // 256
    float* red   = smf + 1280;   // 32
    int tid = threadIdx.x;
    att2s[tid]       = __ldcg(&g_ag[b * 768 + tid]);
    att2s[tid + 256] = __ldcg(&g_ag[b * 768 + 256 + tid]);
    wf[tid]       = wfull[tid];
    wf[tid + 256] = wfull[tid + 256];
    __syncthreads();

    int warp = tid >> 5, lane = tid & 31;
    const __half2* a1 = reinterpret_cast<const __half2*>(g_att1 + (size_t)b * PP * DECD);
    for (int p = warp; p < PP; p += 8) {
        const __half2* row = a1 + (size_t)p * (DECD / 2);
        float acc = 0.f;
#pragma unroll
        for (int i = 0; i < DECD / 64; i++) {
            int d2 = lane + 32 * i;
            float2 v = __half22float2(row[d2]);
            float x0 = v.x + att2s[2 * d2];
            float x1 = v.y + att2s[2 * d2 + 1];
            acc += fmaxf(x0, 0.f) * wf[2 * d2] + fmaxf(x1, 0.f) * wf[2 * d2 + 1];
        }
#pragma unroll
        for (int o = 16; o > 0; o >>= 1) acc += __shfl_xor_sync(0xffffffffu, acc, o);
        if (lane == 0) es[p] = acc;
    }
    __syncthreads();

    float e = es[tid];
    float m = e;
#pragma unroll
    for (int o = 16; o > 0; o >>= 1) m = fmaxf(m, __shfl_xor_sync(0xffffffffu, m, o));
    if (lane == 0) red[warp] = m;
    __syncthreads();
    if (tid == 0) {
        float mm = red[0];
        for (int w = 1; w < 8; w++) mm = fmaxf(mm, red[w]);
        red[16] = mm;
    }
    __syncthreads();
    float ex = expf(e - red[16]);
    float s = ex;
#pragma unroll
    for (int o = 16; o > 0; o >>= 1) s += __shfl_xor_sync(0xffffffffu, s, o);
    if (lane == 0) red[warp] = s;
    __syncthreads();
    if (tid == 0) {
        float ss = 0.f;
        for (int w = 0; w < 8; w++) ss += red[w];
        red[17] = ss;
    }
    __syncthreads();
    float alpha = ex / red[17];
    es[tid] = alpha;
    int active = lens[b] > t;
    alphas_out[((size_t)b * TT + t) * PP + tid] = active ? alpha : 0.f;
    __syncthreads();

    const __half* eb = g_encb + (size_t)b * PP * ENCD;
    float acc = 0.f;
#pragma unroll 8
    for (int p = 0; p < PP; p++) acc += es[p] * __half2float(eb[(size_t)p * ENCD + tid]);
    float gate = __ldcg(&g_ag[b * 768 + 512 + tid]);
    g_xh[b * 768 + tid] = __float2half(gate * acc);
    __syncthreads();
}

// ================= persistent megakernel: all 96 steps =================
__global__ __launch_bounds__(256)
void mega_k(const int* __restrict__ caps, const int* __restrict__ lens,
            const float* __restrict__ wfull,
            const float* __restrict__ bih, const float* __restrict__ bhh,
            const float* __restrict__ fcb,
            float* __restrict__ out_pred, float* __restrict__ out_alph)
{
    extern __shared__ __half sm[];
    float* smf = reinterpret_cast<float*>(sm);
    const int bid = blockIdx.x;
    const int tid = threadIdx.x;
    const int warp = tid >> 5, lane = tid & 31;

    for (int t = 0; t < TT; t++) {
        // ---- phase A: AG GEMM tiles (24) + FC(t-1) tiles (80) ----
        int nwork = 24 + (t > 0 ? 80 : 0);
        for (int w = bid; w < nwork; w += NB) {
            if (w < 24) {
                int mt = w / 6, nt = w % 6;
                int m0 = mt * 64, n0 = nt * 128;
                float acc[2][4][4];
                tile_compute<2>(sm, g_xh + 256, 768, g_wag, 768, m0, n0, 512, acc);
                int wm = (warp & 1) * 32, wn = (warp >> 1) * 32;
#pragma unroll
                for (int mi = 0; mi < 2; mi++)
#pragma unroll
                    for (int hh = 0; hh < 2; hh++) {
                        int m = m0 + wm + mi * 16 + (lane >> 2) + hh * 8;
#pragma unroll
                        for (int ni = 0; ni < 4; ni++)
#pragma unroll
                            for (int j = 0; j < 2; j++) {
                                int n = n0 + wn + ni * 8 + (lane & 3) * 2 + j;
                                float v = acc[mi][ni][hh * 2 + j] + g_bag[n];
                                if (n >= 512) v = sigmoidf(v);
                                g_ag[m * 768 + n] = v;
                            }
                    }
            } else {
                int w2 = w - 24;
                int mt = w2 / 40, nt = w2 % 40;
                int tt = t - 1;
                if (lens[mt * 128] > tt) {
                    int m0 = tt * BB + mt * 128, n0 = nt * 128;
                    float acc[4][4][4];
                    tile_compute<4>(sm, g_hall, DECD, g_wfc, VPAD, m0, n0, 512, acc);
                    int wm = (warp & 1) * 64, wn = (warp >> 1) * 32;
#pragma unroll
                    for (int mi = 0; mi < 4; mi++)
#pragma unroll
                        for (int hh = 0; hh < 2; hh++) {
                            int b = (mt * 128 + wm + mi * 16 + (lane >> 2) + hh * 8);
                            int active = lens[b] > tt;
#pragma unroll
                            for (int ni = 0; ni < 4; ni++)
#pragma unroll
                                for (int j = 0; j < 2; j++) {
                                    int n = n0 + wn + ni * 8 + (lane & 3) * 2 + j;
                                    if (active && n < VV)
                                        out_pred[((size_t)b * TT + tt) * VV + n] =
                                            acc[mi][ni][hh * 2 + j] + fcb[n];
                                }
                        }
                }
            }
        }
        gbar();

        // ---- phase B: attention (256 units) ----
        for (int u = bid; u < BB; u += NB)
            attention_unit(u, t, wfull, lens, out_alph, smf);
        gbar();

        // ---- phase C: gates GEMM (64 tiles, 64x128, K=768) ----
        for (int w = bid; w < 64; w += NB) {
            int mt = w / 16, nt = w % 16;
            int m0 = mt * 64, n0 = nt * 128;
            float acc[2][4][4];
            tile_compute<2>(sm, g_xh, 768, g_wg, GG, m0, n0, 768, acc);
            int wm = (warp & 1) * 32, wn = (warp >> 1) * 32;
#pragma unroll
            for (int mi = 0; mi < 2; mi++)
#pragma unroll
                for (int hh = 0; hh < 2; hh++) {
                    int m = m0 + wm + mi * 16 + (lane >> 2) + hh * 8;
                    int eidx = caps[m * TT + t];
#pragma unroll
                    for (int ni = 0; ni < 4; ni++)
#pragma unroll
                        for (int j = 0; j < 2; j++) {
                            int n = n0 + wn + ni * 8 + (lane & 3) * 2 + j;
                            float v = acc[mi][ni][hh * 2 + j] + bih[n] + bhh[n]
                                      + g_embW[(size_t)eidx * GG + n];
                            g_gates[m * GG + n] = v;
                        }
                }
        }
        gbar();

        // ---- phase D: LSTM cell pointwise ----
        {
            const float* cold = g_c + (t & 1) * (BB * DECD);
            float*       cnew = g_c + ((t + 1) & 1) * (BB * DECD);
            for (int i = bid * 256 + tid; i < BB * DECD; i += NB * 256) {
                int b = i >> 9, d = i & 511;
                const float* gg = g_gates + (size_t)b * GG;
                float ig = sigmoidf(__ldcg(gg + d));
                float fg = sigmoidf(__ldcg(gg + DECD + d));
                float gv = tanhf(__ldcg(gg + 2 * DECD + d));
                float og = sigmoidf(__ldcg(gg + 3 * DECD + d));
                float c = fg * cold[i] + ig * gv;
                cnew[i] = c;
                __half hh = __float2half(og * tanhf(c));
                g_xh[b * 768 + 256 + d] = hh;
                g_hall[((size_t)t * BB + b) * DECD + d] = hh;
            }
        }
        gbar();
    }

    // ---- final FC for t = TT-1 ----
    {
        int tt = TT - 1;
        for (int w = bid; w < 80; w += NB) {
            int mt = w / 40, nt = w % 40;
            if (lens[mt * 128] <= tt) continue;
            int m0 = tt * BB + mt * 128, n0 = nt * 128;
            float acc[4][4][4];
            tile_compute<4>(sm, g_hall, DECD, g_wfc, VPAD, m0, n0, 512, acc);
            int wm = (warp & 1) * 64, wn = (warp >> 1) * 32;
#pragma unroll
            for (int mi = 0; mi < 4; mi++)
#pragma unroll
                for (int hh = 0; hh < 2; hh++) {
                    int b = (mt * 128 + wm + mi * 16 + (lane >> 2) + hh * 8);
                    int active = lens[b] > tt;
#pragma unroll
                    for (int ni = 0; ni < 4; ni++)
#pragma unroll
                        for (int j = 0; j < 2; j++) {
                            int n = n0 + wn + ni * 8 + (lane & 3) * 2 + j;
                            if (active && n < VV)
                                out_pred[((size_t)b * TT + tt) * VV + n] =
                                    acc[mi][ni][hh * 2 + j] + fcb[n];
                        }
                }
        }
    }
}

// ================= standalone precompute GEMM (modes 0 / 4) =================
template<int MODE>
__global__ __launch_bounds__(256)
void hgemm_k(const __half* __restrict__ A, int lda,
             const __half* __restrict__ W, int ldw,
             const float* __restrict__ bias,
             float* __restrict__ Cf, __half* __restrict__ Ch, int ldc,
             int M, int N, int K)
{
    extern __shared__ __half sm[];
    const int tid = threadIdx.x;
    const int warp = tid >> 5, lane = tid & 31;
    const int m0 = blockIdx.y * 128, n0 = blockIdx.x * 128;
    float acc[4][4][4];

    // clamp row for M not multiple of 128 (embW: 5000 rows)
    __half* As = sm;
    __half* Bs = sm + 16384;
#pragma unroll
    for (int i = 0; i < 4; i++)
#pragma unroll
        for (int j = 0; j < 4; j++)
#pragma unroll
            for (int k = 0; k < 4; k++) acc[i][j][k] = 0.f;
    const int nk = K >> 6;
    const int wm = (warp & 1) * 64, wn = (warp >> 1) * 32;

#define PLOAD_A(stage, kc)                                                      \
    {                                                                           \
        _Pragma("unroll")                                                       \
        for (int i = 0; i < 4; i++) {                                           \
            int idx = tid + i * 256;                                            \
            int r = idx >> 3, c = idx & 7;                                      \
            int gm = m0 + r; if (gm >= M) gm = M - 1;                           \
            cp16(As + (stage) * 8192 + r * 64 + (((c ^ r) & 7) << 3),           \
                 A + (size_t)gm * lda + (kc) + c * 8);                          \
        }                                                                       \
    }
#define PLOAD_B(stage, kc)                                                      \
    {                                                                           \
        _Pragma("unroll")                                                       \
        for (int i = 0; i < 4; i++) {                                           \
            int idx = tid + i * 256;                                            \
            int r = idx >> 4, c = idx & 15;                                     \
            int sw = (c & 8) | ((c ^ r) & 7);                                   \
            cp16(Bs + (stage) * 8192 + r * 128 + (sw << 3),                     \
                 W + (size_t)((kc) + r) * ldw + n0 + c * 8);                    \
        }                                                                       \
    }
    PLOAD_A(0, 0); PLOAD_B(0, 0); cp_commit();
    for (int k = 0; k < nk; k++) {
        int cur = k & 1;
        if (k + 1 < nk) { PLOAD_A(cur ^ 1, (k + 1) * 64); PLOAD_B(cur ^ 1, (k + 1) * 64);
                          cp_commit(); cp_wait<1>(); }
        else cp_wait<0>();
        __syncthreads();
        const __half* Ab = As + cur * 8192;
        const __half* Bb = Bs + cur * 8192;
#pragma unroll
        for (int ks = 0; ks < 4; ks++) {
            uint32_t a[4][4], b[2][4];
#pragma unroll
            for (int mi = 0; mi < 4; mi++) {
                int m = wm + mi * 16 + (lane & 15);
                int kch = ks * 2 + (lane >> 4);
                ldm_x4(a[mi], smem_u32(Ab + m * 64 + (((kch ^ m) & 7) << 3)));
            }
#pragma unroll
            for (int ni = 0; ni < 2; ni++) {
                int kk = ks * 16 + (lane & 15);
                int nch = (wn >> 3) + ni * 2 + (lane >> 4);
                int sw = (nch & 8) | ((nch ^ kk) & 7);
                ldm_x4_t(b[ni], smem_u32(Bb + kk * 128 + (sw << 3)));
            }
#pragma unroll
            for (int mi = 0; mi < 4; mi++)
#pragma unroll
                for (int ni = 0; ni < 4; ni++)
                    mma16816(acc[mi][ni], a[mi], &b[ni >> 1][(ni & 1) * 2]);
        }
        __syncthreads();
    }
#undef PLOAD_A
#undef PLOAD_B
#pragma unroll
    for (int mi = 0; mi < 4; mi++)
#pragma unroll
        for (int hh = 0; hh < 2; hh++) {
            int m = m0 + wm + mi * 16 + (lane >> 2) + hh * 8;
            if (m >= M) continue;
#pragma unroll
            for (int ni = 0; ni < 4; ni++)
#pragma unroll
                for (int j = 0; j < 2; j++) {
                    int n = n0 + wn + ni * 8 + (lane & 3) * 2 + j;
                    float v = acc[mi][ni][hh * 2 + j];
                    if (bias) v += bias[n];
                    if (MODE == 0) Cf[(size_t)m * ldc + n] = v;
                    else           Ch[(size_t)m * ldc + n] = __float2half(v);
                }
        }
}

// ================= small kernels =================
__global__ void cvt_k(const float* __restrict__ src, __half* __restrict__ dst,
                      int rows, int cols, int sld, int dld, int valid)
{
    int n = rows * cols;
    for (int i = blockIdx.x * blockDim.x + threadIdx.x; i < n; i += gridDim.x * blockDim.x) {
        int r = i / cols, c = i - r * cols;
        float v = (c < valid) ? src[(size_t)r * sld + c] : 0.f;
        dst[(size_t)r * dld + c] = __float2half(v);
    }
}

__global__ void mean_k(const float* __restrict__ enc)
{
    int b = blockIdx.x, e = threadIdx.x;
    const float* p = enc + (size_t)b * PP * ENCD + e;
    float s = 0.f;
#pragma unroll 8
    for (int pp = 0; pp < PP; pp++) s += p[(size_t)pp * ENCD];
    g_mean16[b * ENCD + e] = __float2half(s * (1.f / PP));
}

__global__ void bag_k(const float* __restrict__ b1, const float* __restrict__ b2)
{
    int i = threadIdx.x + blockIdx.x * blockDim.x;
    if (i < 512) g_bag[i] = b1[i];
    else if (i < 768) g_bag[i] = b2[i - 512];
}

__global__ void h0c_k()
{
    int b = blockIdx.x, d = threadIdx.x;
    g_xh[b * 768 + 256 + d] = __float2half(g_h[b * DECD + d]);
}

__global__ void lens_k(const int* __restrict__ lens, float* __restrict__ o)
{
    o[threadIdx.x] = (float)lens[threadIdx.x];
}

// ================= host orchestration =================
static inline int cgrid(int n) { int g = (n + 255) / 256; return g > 4096 ? 4096 : g; }

extern "C" void kernel_launch(void* const* d_in, const int* in_sizes, int n_in,
                              void* d_out, int out_size)
{
    const float* enc        = (const float*)d_in[0];
    const int*   caps       = (const int*)d_in[1];
    const int*   lens       = (const int*)d_in[2];
    const float* embedding  = (const float*)d_in[3];
    const float* enc_att_w  = (const float*)d_in[4];
    const float* enc_att_b  = (const float*)d_in[5];
    const float* dec_att_w  = (const float*)d_in[6];
    const float* dec_att_b  = (const float*)d_in[7];
    const float* full_att_w = (const float*)d_in[8];
    const float* lstm_wih   = (const float*)d_in[10];
    const float* lstm_whh   = (const float*)d_in[11];
    const float* lstm_bih   = (const float*)d_in[12];
    const float* lstm_bhh   = (const float*)d_in[13];
    const float* init_h_w   = (const float*)d_in[14];
    const float* init_h_b   = (const float*)d_in[15];
    const float* init_c_w   = (const float*)d_in[16];
    const float* init_c_b   = (const float*)d_in[17];
    const float* f_beta_w   = (const float*)d_in[18];
    const float* f_beta_b   = (const float*)d_in[19];
    const float* fc_w       = (const float*)d_in[20];
    const float* fc_b       = (const float*)d_in[21];

    float* out      = (float*)d_out;
    float* out_pred = out;
    float* out_lens = out + (size_t)BB * TT * VV;
    float* out_alph = out_lens + BB;

    cudaFuncSetAttribute(hgemm_k<0>, cudaFuncAttributeMaxDynamicSharedMemorySize, SMEMSZ);
    cudaFuncSetAttribute(hgemm_k<4>, cudaFuncAttributeMaxDynamicSharedMemorySize, SMEMSZ);
    cudaFuncSetAttribute(mega_k,     cudaFuncAttributeMaxDynamicSharedMemorySize, SMEMSZ);

    cudaMemsetAsync(d_out, 0, (size_t)out_size * sizeof(float));

    __half *p_encb, *p_emb16, *p_mean16, *p_att1;
    __half *p_wag, *p_wg, *p_wtop, *p_wfc, *p_wenc, *p_wih0, *p_wic0;
    float *p_h, *p_c, *p_embW;
    cudaGetSymbolAddress((void**)&p_encb, g_encb);
    cudaGetSymbolAddress((void**)&p_emb16, g_emb16);
    cudaGetSymbolAddress((void**)&p_mean16, g_mean16);
    cudaGetSymbolAddress((void**)&p_att1, g_att1);
    cudaGetSymbolAddress((void**)&p_wag, g_wag);
    cudaGetSymbolAddress((void**)&p_wg, g_wg);
    cudaGetSymbolAddress((void**)&p_wtop, g_wtop);
    cudaGetSymbolAddress((void**)&p_wfc, g_wfc);
    cudaGetSymbolAddress((void**)&p_wenc, g_wenc);
    cudaGetSymbolAddress((void**)&p_wih0, g_wih0);
    cudaGetSymbolAddress((void**)&p_wic0, g_wic0);
    cudaGetSymbolAddress((void**)&p_h, g_h);
    cudaGetSymbolAddress((void**)&p_c, g_c);
    cudaGetSymbolAddress((void**)&p_embW, g_embW);

    // ---- conversions ----
    cvt_k<<<cgrid(BB * PP * ENCD), 256>>>(enc, p_encb, BB * PP, ENCD, ENCD, ENCD, ENCD);
    cvt_k<<<cgrid(VV * EE), 256>>>(embedding, p_emb16, VV, EE, EE, EE, EE);
    cvt_k<<<cgrid(512 * 512), 256>>>(dec_att_w, p_wag, 512, 512, 512, 768, 512);
    cvt_k<<<cgrid(512 * 256), 256>>>(f_beta_w, p_wag + 512, 512, 256, 256, 768, 256);
    cvt_k<<<cgrid(256 * GG), 256>>>(lstm_wih, p_wtop, 256, GG, GG, GG, GG);
    cvt_k<<<cgrid(256 * GG), 256>>>(lstm_wih + (size_t)EE * GG, p_wg, 256, GG, GG, GG, GG);
    cvt_k<<<cgrid(512 * GG), 256>>>(lstm_whh, p_wg + (size_t)256 * GG, 512, GG, GG, GG, GG);
    cvt_k<<<cgrid(512 * VPAD), 256>>>(fc_w, p_wfc, 512, VPAD, VV, VPAD, VV);
    cvt_k<<<cgrid(256 * 512), 256>>>(enc_att_w, p_wenc, 256, 512, 512, 512, 512);
    cvt_k<<<cgrid(256 * 512), 256>>>(init_h_w, p_wih0, 256, 512, 512, 512, 512);
    cvt_k<<<cgrid(256 * 512), 256>>>(init_c_w, p_wic0, 256, 512, 512, 512, 512);
    bag_k<<<3, 256>>>(dec_att_b, f_beta_b);
    mean_k<<<BB, 256>>>(enc);

    // ---- one-time TC GEMMs ----
    hgemm_k<0><<<dim3(DECD / 128, BB / 128), 256, SMEMSZ>>>(p_mean16, ENCD, p_wih0, DECD,
        init_h_b, p_h, nullptr, DECD, BB, DECD, ENCD);
    hgemm_k<0><<<dim3(DECD / 128, BB / 128), 256, SMEMSZ>>>(p_mean16, ENCD, p_wic0, DECD,
        init_c_b, p_c, nullptr, DECD, BB, DECD, ENCD);
    h0c_k<<<BB, DECD>>>();
    hgemm_k<4><<<dim3(DECD / 128, (BB * PP) / 128), 256, SMEMSZ>>>(p_encb, ENCD, p_wenc, DECD,
        enc_att_b, nullptr, p_att1, DECD, BB * PP, DECD, ENCD);
    hgemm_k<0><<<dim3(GG / 128, (VV + 127) / 128), 256, SMEMSZ>>>(p_emb16, EE, p_wtop, GG,
        nullptr, p_embW, nullptr, GG, VV, GG, EE);

    // ---- persistent megakernel: all 96 timesteps + embedded fc ----
    mega_k<<<NB, 256, SMEMSZ>>>(caps, lens, full_att_w, lstm_bih, lstm_bhh, fc_b,
                                out_pred, out_alph);

    lens_k<<<1, BB>>>(lens, out_lens);
}